// round 8
// baseline (speedup 1.0000x reference)
#include <cuda_runtime.h>
#include <cuda_pipeline.h>
#include <mma.h>
#include <math.h>

using namespace nvcuda;

#define NMAX   50000
#define EMAX   800000
#define TOTMAX (NMAX + EMAX)
#define F      128
#define NPAD   (NMAX + 128)   // slack so tail-block wmma stores can't overflow

// ---------------- device scratch (no allocations allowed) ----------------
__device__ float g_xp[NPAD * F];        // x @ W
__device__ float g_asrc[NMAX];          // xp . att_src
__device__ float g_adst[NMAX];          // xp . att_dst
__device__ int   g_deg[NMAX];           // per-dst degree (incl self loop)
__device__ int   g_offs[NMAX + 1];      // CSR offsets
__device__ int   g_rank[EMAX];          // per-edge rank within its dst segment
__device__ int   g_csr[TOTMAX];         // CSR: source node per slot
__device__ int   g_bsum[256];           // scan: per-block sums
__device__ int   g_boff[256];           // scan: per-block exclusive offsets
__device__ int   g_is64;                // edge_index dtype flag

// ---------------- fused probe (1 warp of block 0) + degree init ----------------
__global__ void probe_init_kernel(const unsigned int* __restrict__ w, int E, int N) {
    int i = blockIdx.x * blockDim.x + threadIdx.x;
    if (i < N) g_deg[i] = 1;                       // self loop
    if (blockIdx.x == 0 && threadIdx.x < 32) {
        int samples = E < 1024 ? E : 1024;
        int bad = 0;
        for (int k = threadIdx.x; k < samples; k += 32)
            bad |= (w[2 * k + 1] != 0u) ? 1 : 0;
        unsigned int b = __ballot_sync(0xffffffffu, bad);
        if (threadIdx.x == 0) g_is64 = (b == 0u) ? 1 : 0;
    }
}

__device__ __forceinline__ int edge_at(const void* ebuf, long long idx, int is64) {
    if (is64) return (int)((const long long*)ebuf)[idx];
    return ((const int*)ebuf)[idx];
}

// ---------------- histogram of dst + per-edge rank ----------------
__global__ void hist_kernel(const void* __restrict__ edges, int E) {
    int e = blockIdx.x * blockDim.x + threadIdx.x;
    if (e >= E) return;
    int is64 = g_is64;
    int d = edge_at(edges, (long long)E + e, is64);
    g_rank[e] = atomicAdd(&g_deg[d], 1);   // old value >= 1 (slot 0 = self loop)
}

// ---------------- GEMM: persistent CTAs, wmma tf32, cp.async pipelined --------
// grid = #SMs. Each block stages W (128x128) ONCE, then loops over its M-tiles
// (BM=128). A chunks (BK=32) are double-buffered across the whole linear chunk
// sequence, spanning tile boundaries -> no wave drain, no W restaging.
#define BM 128
#define BK 32
#define LDA 40    // 32 + 8 pad
#define LDB 136   // 128 + 8 pad
#define GEMM_SMEM_FLOATS (128 * LDB + 2 * BM * LDA)
#define GEMM_SMEM_BYTES  (GEMM_SMEM_FLOATS * 4)

__global__ __launch_bounds__(256)
void gemm_kernel(const float* __restrict__ x, const float* __restrict__ W,
                 const float* __restrict__ att_src, const float* __restrict__ att_dst,
                 int N, int tiles, int gridSz) {
    extern __shared__ float smem[];
    float* Ws = smem;                    // [128][LDB]
    float* As = smem + 128 * LDB;        // [2][BM][LDA]

    int tid  = threadIdx.x;
    int warp = tid >> 5;
    int lane = tid & 31;
    int warp_m = warp >> 1;
    int warp_n = warp & 1;

    // my tiles: blockIdx.x, +gridSz, ... ; linear chunks q = 0..4*nmine-1
    int nmine = 0;
    for (int t = blockIdx.x; t < tiles; t += gridSz) nmine++;
    if (nmine == 0) return;
    int Q = nmine * 4;

    auto tileRow0 = [&](int q) { return (blockIdx.x + (q >> 2) * gridSz) * BM; };

    // stage A chunk q into buffer q&1 (async)
    auto stageA = [&](int q) {
        int row0 = tileRow0(q);
        int kb = q & 3;
        float* base = As + (q & 1) * BM * LDA;
#pragma unroll
        for (int it = 0; it < 4; it++) {
            int item = tid + it * 256;       // 1024 items = 128 rows x 8 float4
            int m = item >> 3, kq = item & 7;
            int gr = row0 + m;
            float* dst = base + m * LDA + kq * 4;
            if (gr < N) {
                __pipeline_memcpy_async(dst, x + (long long)gr * F + kb * 32 + kq * 4, 16);
            } else {
                dst[0] = 0.f; dst[1] = 0.f; dst[2] = 0.f; dst[3] = 0.f;
            }
        }
        __pipeline_commit();
    };

    stageA(0);
    // stage full W once: 128 rows x 32 float4
#pragma unroll
    for (int it = 0; it < 16; it++) {
        int item = tid + it * 256;
        int k = item >> 5, nq = item & 31;
        __pipeline_memcpy_async(Ws + k * LDB + nq * 4, W + (long long)k * F + nq * 4, 16);
    }
    __pipeline_commit();

    wmma::fragment<wmma::accumulator, 16, 16, 8, float> acc[2][4];
#pragma unroll
    for (int mt = 0; mt < 2; mt++)
#pragma unroll
        for (int nt = 0; nt < 4; nt++)
            wmma::fill_fragment(acc[mt][nt], 0.0f);

    __pipeline_wait_prior(0);
    __syncthreads();

    for (int q = 0; q < Q; q++) {
        if (q + 1 < Q) stageA(q + 1);            // overlap next chunk with compute
        const float* Abuf = As + (q & 1) * BM * LDA;
        int kb = q & 3;

#pragma unroll
        for (int kk = 0; kk < 4; kk++) {
            wmma::fragment<wmma::matrix_a, 16, 16, 8, wmma::precision::tf32, wmma::row_major> af[2];
            wmma::fragment<wmma::matrix_b, 16, 16, 8, wmma::precision::tf32, wmma::row_major> bf[4];
#pragma unroll
            for (int mt = 0; mt < 2; mt++) {
                wmma::load_matrix_sync(af[mt], Abuf + (warp_m * 32 + mt * 16) * LDA + kk * 8, LDA);
#pragma unroll
                for (int i = 0; i < af[mt].num_elements; i++)
                    af[mt].x[i] = wmma::__float_to_tf32(af[mt].x[i]);
            }
#pragma unroll
            for (int nt = 0; nt < 4; nt++) {
                wmma::load_matrix_sync(bf[nt], Ws + (kb * 32 + kk * 8) * LDB + warp_n * 64 + nt * 16, LDB);
#pragma unroll
                for (int i = 0; i < bf[nt].num_elements; i++)
                    bf[nt].x[i] = wmma::__float_to_tf32(bf[nt].x[i]);
            }
#pragma unroll
            for (int mt = 0; mt < 2; mt++)
#pragma unroll
                for (int nt = 0; nt < 4; nt++)
                    wmma::mma_sync(acc[mt][nt], af[mt], bf[nt], acc[mt][nt]);
        }

        if (kb == 3) {
            // tile finished: epilogue (stores + fused attention dots), then reset acc
            int row0 = tileRow0(q);
#pragma unroll
            for (int mt = 0; mt < 2; mt++)
#pragma unroll
                for (int nt = 0; nt < 4; nt++)
                    wmma::store_matrix_sync(
                        &g_xp[(long long)(row0 + warp_m * 32 + mt * 16) * F + warp_n * 64 + nt * 16],
                        acc[mt][nt], F, wmma::mem_row_major);
            __syncthreads();   // block's g_xp stores visible to all its warps

            {
                float4 a = ((const float4*)att_src)[lane];
                float4 b = ((const float4*)att_dst)[lane];
                const float4* xp4 = (const float4*)g_xp;
#pragma unroll
                for (int r = 0; r < 16; r++) {
                    int gr = row0 + warp * 16 + r;
                    if (gr >= N) break;
                    float4 v = xp4[(long long)gr * 32 + lane];
                    float ps = v.x * a.x + v.y * a.y + v.z * a.z + v.w * a.w;
                    float pd = v.x * b.x + v.y * b.y + v.z * b.z + v.w * b.w;
#pragma unroll
                    for (int o = 16; o; o >>= 1) {
                        ps += __shfl_down_sync(0xffffffffu, ps, o);
                        pd += __shfl_down_sync(0xffffffffu, pd, o);
                    }
                    if (lane == 0) { g_asrc[gr] = ps; g_adst[gr] = pd; }
                }
            }
#pragma unroll
            for (int mt = 0; mt < 2; mt++)
#pragma unroll
                for (int nt = 0; nt < 4; nt++)
                    wmma::fill_fragment(acc[mt][nt], 0.0f);
        }

        if (q + 1 < Q) { __pipeline_wait_prior(0); __syncthreads(); }
    }
}

// ---------------- parallel scan: A) block sums ----------------
__global__ void scanA_kernel(int N) {
    __shared__ int sh[256];
    int t = threadIdx.x;
    int i = blockIdx.x * 256 + t;
    sh[t] = (i < N) ? g_deg[i] : 0;
    __syncthreads();
    for (int o = 128; o; o >>= 1) {
        if (t < o) sh[t] += sh[t + o];
        __syncthreads();
    }
    if (t == 0) g_bsum[blockIdx.x] = sh[0];
}

// ---------------- parallel scan: B) scan of block sums (1 block) --------------
__global__ void scanB_kernel(int nb, int N) {
    __shared__ int sh[256];
    int t = threadIdx.x;
    int v = (t < nb) ? g_bsum[t] : 0;
    sh[t] = v;
    __syncthreads();
    for (int o = 1; o < 256; o <<= 1) {
        int u = (t >= o) ? sh[t - o] : 0;
        __syncthreads();
        sh[t] += u;
        __syncthreads();
    }
    if (t < nb) g_boff[t] = sh[t] - v;      // exclusive
    if (t == 255) g_offs[N] = sh[255];      // total
}

// ---------------- parallel scan: C) apply + self-loop placement ---------------
__global__ void scanC_kernel(int N) {
    __shared__ int sh[256];
    int t = threadIdx.x;
    int i = blockIdx.x * 256 + t;
    int v = (i < N) ? g_deg[i] : 0;
    sh[t] = v;
    __syncthreads();
    for (int o = 1; o < 256; o <<= 1) {
        int u = (t >= o) ? sh[t - o] : 0;
        __syncthreads();
        sh[t] += u;
        __syncthreads();
    }
    if (i < N) {
        int off = g_boff[blockIdx.x] + sh[t] - v;
        g_offs[i] = off;
        g_csr[off] = i;                      // self loop at slot 0 of segment
    }
}

// ---------------- CSR fill (atomic-free via precomputed rank) ----------------
__global__ void fill_kernel(const void* __restrict__ edges, int E) {
    int e = blockIdx.x * blockDim.x + threadIdx.x;
    if (e >= E) return;
    int is64 = g_is64;
    int s = edge_at(edges, e, is64);
    int d = edge_at(edges, (long long)E + e, is64);
    g_csr[__ldg(&g_offs[d]) + g_rank[e]] = s;
}

// ---------------- aggregate: warp per dst, chunked cooperative prefetch -------
__global__ void aggregate_kernel(const float* __restrict__ bias,
                                 float* __restrict__ out, int N) {
    int warp = (blockIdx.x * blockDim.x + threadIdx.x) >> 5;
    int lane = threadIdx.x & 31;
    if (warp >= N) return;

    int beg = g_offs[warp];
    int end = g_offs[warp + 1];
    float adi = g_adst[warp];

    float s = 0.f;
    float4 acc = make_float4(0.f, 0.f, 0.f, 0.f);
    const float4* xp4 = (const float4*)g_xp;

    for (int c = beg; c < end; c += 32) {
        int idx = c + lane;
        bool valid = idx < end;
        int j = __ldg(&g_csr[valid ? idx : beg]);
        float e = __ldg(&g_asrc[j]) + adi;
        e = fmaxf(e, 0.2f * e);              // leaky_relu(0.2)
        float p = valid ? __expf(e) : 0.f;

        int cnt = end - c; if (cnt > 32) cnt = 32;
#pragma unroll 8
        for (int t = 0; t < cnt; t++) {
            int jj   = __shfl_sync(0xffffffffu, j, t);
            float pp = __shfl_sync(0xffffffffu, p, t);
            float4 xv = xp4[(long long)jj * 32 + lane];
            s += pp;
            acc.x = fmaf(pp, xv.x, acc.x);
            acc.y = fmaf(pp, xv.y, acc.y);
            acc.z = fmaf(pp, xv.z, acc.z);
            acc.w = fmaf(pp, xv.w, acc.w);
        }
    }

    float inv = 1.0f / s;
    float4 b = ((const float4*)bias)[lane];
    float4 o;
    o.x = fmaf(acc.x, inv, b.x);
    o.y = fmaf(acc.y, inv, b.y);
    o.z = fmaf(acc.z, inv, b.z);
    o.w = fmaf(acc.w, inv, b.w);
    ((float4*)out)[(long long)warp * 32 + lane] = o;
}

// ---------------- launch ----------------
extern "C" void kernel_launch(void* const* d_in, const int* in_sizes, int n_in,
                              void* d_out, int out_size) {
    const float* x       = (const float*)d_in[0];
    const float* W       = (const float*)d_in[1];
    const float* att_src = (const float*)d_in[2];
    const float* att_dst = (const float*)d_in[3];
    const float* bias    = (const float*)d_in[4];
    const void*  edges   = d_in[5];

    int N = in_sizes[0] / F;
    int E = in_sizes[5] / 2;
    if (N > NMAX) N = NMAX;
    if (E > EMAX) E = EMAX;

    int nb = (N + 255) / 256;              // scan blocks (<= 256)
    int tiles = (N + BM - 1) / BM;
    int gridSz = tiles < 148 ? tiles : 148; // persistent: 1 block per SM

    cudaFuncSetAttribute(gemm_kernel, cudaFuncAttributeMaxDynamicSharedMemorySize,
                         GEMM_SMEM_BYTES);

    // order chosen so the profiler's idx-3 slot captures gemm_kernel
    probe_init_kernel<<<(N + 255) / 256, 256>>>((const unsigned int*)edges, E, N);
    hist_kernel<<<(E + 255) / 256, 256>>>(edges, E);
    scanA_kernel<<<nb, 256>>>(N);
    gemm_kernel<<<gridSz, 256, GEMM_SMEM_BYTES>>>(x, W, att_src, att_dst, N, tiles, gridSz);
    scanB_kernel<<<1, 256>>>(nb, N);
    scanC_kernel<<<nb, 256>>>(N);
    fill_kernel<<<(E + 255) / 256, 256>>>(edges, E);
    aggregate_kernel<<<(N + 7) / 8, 256>>>(bias, (float*)d_out, N);
}

// round 9
// speedup vs baseline: 1.1492x; 1.1492x over previous
#include <cuda_runtime.h>
#include <cuda_pipeline.h>
#include <mma.h>
#include <math.h>

using namespace nvcuda;

#define NMAX   50000
#define EMAX   800000
#define TOTMAX (NMAX + EMAX)
#define F      128
#define NPAD   (NMAX + 128)   // slack so tail-block wmma stores can't overflow

// ---------------- device scratch (no allocations allowed) ----------------
__device__ float g_xp[NPAD * F];        // x @ W
__device__ float g_asrc[NMAX];          // xp . att_src
__device__ float g_adst[NMAX];          // xp . att_dst
__device__ int   g_deg[NMAX];           // per-dst degree (incl self loop)
__device__ int   g_offs[NMAX + 1];      // CSR offsets
__device__ int   g_rank[EMAX];          // per-edge rank within its dst segment
__device__ int   g_csr[TOTMAX];         // CSR: source node per slot
__device__ int   g_bsum[256];           // scan: per-block sums
__device__ int   g_boff[256];           // scan: per-block exclusive offsets
__device__ int   g_is64;                // edge_index dtype flag

// ---------------- fused probe (1 warp of block 0) + degree init ----------------
__global__ void probe_init_kernel(const unsigned int* __restrict__ w, int E, int N) {
    int i = blockIdx.x * blockDim.x + threadIdx.x;
    if (i < N) g_deg[i] = 1;                       // self loop
    if (blockIdx.x == 0 && threadIdx.x < 32) {
        int samples = E < 1024 ? E : 1024;
        int bad = 0;
        for (int k = threadIdx.x; k < samples; k += 32)
            bad |= (w[2 * k + 1] != 0u) ? 1 : 0;
        unsigned int b = __ballot_sync(0xffffffffu, bad);
        if (threadIdx.x == 0) g_is64 = (b == 0u) ? 1 : 0;
    }
}

__device__ __forceinline__ int edge_at(const void* ebuf, long long idx, int is64) {
    if (is64) return (int)((const long long*)ebuf)[idx];
    return ((const int*)ebuf)[idx];
}

// ---------------- histogram of dst + per-edge rank ----------------
__global__ void hist_kernel(const void* __restrict__ edges, int E) {
    int e = blockIdx.x * blockDim.x + threadIdx.x;
    if (e >= E) return;
    int is64 = g_is64;
    int d = edge_at(edges, (long long)E + e, is64);
    g_rank[e] = atomicAdd(&g_deg[d], 1);   // old value >= 1 (slot 0 = self loop)
}

// ---------------- GEMM (wmma tf32, cp.async pipelined) + fused dots ----------
// R6/R7 version (measured 45us): 391 blocks, W staged per block, A double-buffered.
#define BM 128
#define BK 32
#define LDA 40    // 32 + 8 pad
#define LDB 136   // 128 + 8 pad
#define GEMM_SMEM_FLOATS (128 * LDB + 2 * BM * LDA)
#define GEMM_SMEM_BYTES  (GEMM_SMEM_FLOATS * 4)

__global__ __launch_bounds__(256)
void gemm_kernel(const float* __restrict__ x, const float* __restrict__ W,
                 const float* __restrict__ att_src, const float* __restrict__ att_dst,
                 int N) {
    extern __shared__ float smem[];
    float* Ws = smem;                    // [128][LDB]
    float* As = smem + 128 * LDB;        // [2][BM][LDA]

    int tid  = threadIdx.x;
    int warp = tid >> 5;
    int lane = tid & 31;
    int warp_m = warp >> 1;
    int warp_n = warp & 1;
    int row0 = blockIdx.x * BM;

    auto stageA = [&](int kb, int buf) {
        float* base = As + buf * BM * LDA;
#pragma unroll
        for (int it = 0; it < 4; it++) {
            int item = tid + it * 256;       // 1024 items = 128 rows x 8 float4
            int m = item >> 3, kq = item & 7;
            int gr = row0 + m;
            float* dst = base + m * LDA + kq * 4;
            if (gr < N) {
                __pipeline_memcpy_async(dst, x + (long long)gr * F + kb * 32 + kq * 4, 16);
            } else {
                dst[0] = 0.f; dst[1] = 0.f; dst[2] = 0.f; dst[3] = 0.f;
            }
        }
        __pipeline_commit();
    };

    stageA(0, 0);
#pragma unroll
    for (int it = 0; it < 16; it++) {
        int item = tid + it * 256;
        int k = item >> 5, nq = item & 31;
        __pipeline_memcpy_async(Ws + k * LDB + nq * 4, W + (long long)k * F + nq * 4, 16);
    }
    __pipeline_commit();

    wmma::fragment<wmma::accumulator, 16, 16, 8, float> acc[2][4];
#pragma unroll
    for (int mt = 0; mt < 2; mt++)
#pragma unroll
        for (int nt = 0; nt < 4; nt++)
            wmma::fill_fragment(acc[mt][nt], 0.0f);

    __pipeline_wait_prior(0);
    __syncthreads();

    for (int kb = 0; kb < 4; kb++) {
        if (kb < 3) stageA(kb + 1, (kb + 1) & 1);
        const float* Abuf = As + (kb & 1) * BM * LDA;

#pragma unroll
        for (int kk = 0; kk < 4; kk++) {
            wmma::fragment<wmma::matrix_a, 16, 16, 8, wmma::precision::tf32, wmma::row_major> af[2];
            wmma::fragment<wmma::matrix_b, 16, 16, 8, wmma::precision::tf32, wmma::row_major> bf[4];
#pragma unroll
            for (int mt = 0; mt < 2; mt++) {
                wmma::load_matrix_sync(af[mt], Abuf + (warp_m * 32 + mt * 16) * LDA + kk * 8, LDA);
#pragma unroll
                for (int i = 0; i < af[mt].num_elements; i++)
                    af[mt].x[i] = wmma::__float_to_tf32(af[mt].x[i]);
            }
#pragma unroll
            for (int nt = 0; nt < 4; nt++) {
                wmma::load_matrix_sync(bf[nt], Ws + (kb * 32 + kk * 8) * LDB + warp_n * 64 + nt * 16, LDB);
#pragma unroll
                for (int i = 0; i < bf[nt].num_elements; i++)
                    bf[nt].x[i] = wmma::__float_to_tf32(bf[nt].x[i]);
            }
#pragma unroll
            for (int mt = 0; mt < 2; mt++)
#pragma unroll
                for (int nt = 0; nt < 4; nt++)
                    wmma::mma_sync(acc[mt][nt], af[mt], bf[nt], acc[mt][nt]);
        }

        if (kb < 3) { __pipeline_wait_prior(0); __syncthreads(); }
    }

#pragma unroll
    for (int mt = 0; mt < 2; mt++)
#pragma unroll
        for (int nt = 0; nt < 4; nt++)
            wmma::store_matrix_sync(
                &g_xp[(long long)(row0 + warp_m * 32 + mt * 16) * F + warp_n * 64 + nt * 16],
                acc[mt][nt], F, wmma::mem_row_major);

    __syncthreads();

    // fused attention dots: warp w handles rows row0 + w*16 .. +15
    {
        float4 a = ((const float4*)att_src)[lane];
        float4 b = ((const float4*)att_dst)[lane];
        const float4* xp4 = (const float4*)g_xp;
#pragma unroll
        for (int r = 0; r < 16; r++) {
            int gr = row0 + warp * 16 + r;
            if (gr >= N) break;
            float4 v = xp4[(long long)gr * 32 + lane];
            float ps = v.x * a.x + v.y * a.y + v.z * a.z + v.w * a.w;
            float pd = v.x * b.x + v.y * b.y + v.z * b.z + v.w * b.w;
#pragma unroll
            for (int o = 16; o; o >>= 1) {
                ps += __shfl_down_sync(0xffffffffu, ps, o);
                pd += __shfl_down_sync(0xffffffffu, pd, o);
            }
            if (lane == 0) { g_asrc[gr] = ps; g_adst[gr] = pd; }
        }
    }
}

// ---------------- parallel scan: A) block sums ----------------
__global__ void scanA_kernel(int N) {
    __shared__ int sh[256];
    int t = threadIdx.x;
    int i = blockIdx.x * 256 + t;
    sh[t] = (i < N) ? g_deg[i] : 0;
    __syncthreads();
    for (int o = 128; o; o >>= 1) {
        if (t < o) sh[t] += sh[t + o];
        __syncthreads();
    }
    if (t == 0) g_bsum[blockIdx.x] = sh[0];
}

// ---------------- parallel scan: B) scan of block sums (1 block) --------------
__global__ void scanB_kernel(int nb, int N) {
    __shared__ int sh[256];
    int t = threadIdx.x;
    int v = (t < nb) ? g_bsum[t] : 0;
    sh[t] = v;
    __syncthreads();
    for (int o = 1; o < 256; o <<= 1) {
        int u = (t >= o) ? sh[t - o] : 0;
        __syncthreads();
        sh[t] += u;
        __syncthreads();
    }
    if (t < nb) g_boff[t] = sh[t] - v;      // exclusive
    if (t == 255) g_offs[N] = sh[255];      // total
}

// ---------------- parallel scan: C) apply + self-loop placement ---------------
__global__ void scanC_kernel(int N) {
    __shared__ int sh[256];
    int t = threadIdx.x;
    int i = blockIdx.x * 256 + t;
    int v = (i < N) ? g_deg[i] : 0;
    sh[t] = v;
    __syncthreads();
    for (int o = 1; o < 256; o <<= 1) {
        int u = (t >= o) ? sh[t - o] : 0;
        __syncthreads();
        sh[t] += u;
        __syncthreads();
    }
    if (i < N) {
        int off = g_boff[blockIdx.x] + sh[t] - v;
        g_offs[i] = off;
        g_csr[off] = i;                      // self loop at slot 0 of segment
    }
}

// ---------------- CSR fill (atomic-free via precomputed rank) ----------------
__global__ void fill_kernel(const void* __restrict__ edges, int E) {
    int e = blockIdx.x * blockDim.x + threadIdx.x;
    if (e >= E) return;
    int is64 = g_is64;
    int s = edge_at(edges, e, is64);
    int d = edge_at(edges, (long long)E + e, is64);
    g_csr[__ldg(&g_offs[d]) + g_rank[e]] = s;
}

// ---------------- aggregate: warp per dst, chunked cooperative prefetch -------
__global__ void aggregate_kernel(const float* __restrict__ bias,
                                 float* __restrict__ out, int N) {
    int warp = (blockIdx.x * blockDim.x + threadIdx.x) >> 5;
    int lane = threadIdx.x & 31;
    if (warp >= N) return;

    int beg = g_offs[warp];
    int end = g_offs[warp + 1];
    float adi = g_adst[warp];

    float s = 0.f;
    float4 acc = make_float4(0.f, 0.f, 0.f, 0.f);
    const float4* xp4 = (const float4*)g_xp;

    for (int c = beg; c < end; c += 32) {
        int idx = c + lane;
        bool valid = idx < end;
        int j = __ldg(&g_csr[valid ? idx : beg]);
        float e = __ldg(&g_asrc[j]) + adi;
        e = fmaxf(e, 0.2f * e);              // leaky_relu(0.2)
        float p = valid ? __expf(e) : 0.f;

        int cnt = end - c; if (cnt > 32) cnt = 32;
#pragma unroll 8
        for (int t = 0; t < cnt; t++) {
            int jj   = __shfl_sync(0xffffffffu, j, t);
            float pp = __shfl_sync(0xffffffffu, p, t);
            float4 xv = xp4[(long long)jj * 32 + lane];
            s += pp;
            acc.x = fmaf(pp, xv.x, acc.x);
            acc.y = fmaf(pp, xv.y, acc.y);
            acc.z = fmaf(pp, xv.z, acc.z);
            acc.w = fmaf(pp, xv.w, acc.w);
        }
    }

    float inv = 1.0f / s;
    float4 b = ((const float4*)bias)[lane];
    float4 o;
    o.x = fmaf(acc.x, inv, b.x);
    o.y = fmaf(acc.y, inv, b.y);
    o.z = fmaf(acc.z, inv, b.z);
    o.w = fmaf(acc.w, inv, b.w);
    ((float4*)out)[(long long)warp * 32 + lane] = o;
}

// ---------------- launch: fork-join over a second stream ----------------
// Chain A (default stream): gemm.  Chain B (s2): edge pipeline.  Join before
// aggregate. Event fork/join is graph-capture legal; stream/events are host
// resources created per call (kernel_launch runs only twice: correctness+capture).
extern "C" void kernel_launch(void* const* d_in, const int* in_sizes, int n_in,
                              void* d_out, int out_size) {
    const float* x       = (const float*)d_in[0];
    const float* W       = (const float*)d_in[1];
    const float* att_src = (const float*)d_in[2];
    const float* att_dst = (const float*)d_in[3];
    const float* bias    = (const float*)d_in[4];
    const void*  edges   = d_in[5];

    int N = in_sizes[0] / F;
    int E = in_sizes[5] / 2;
    if (N > NMAX) N = NMAX;
    if (E > EMAX) E = EMAX;

    int nb = (N + 255) / 256;   // scan blocks (<= 256)

    cudaFuncSetAttribute(gemm_kernel, cudaFuncAttributeMaxDynamicSharedMemorySize,
                         GEMM_SMEM_BYTES);

    cudaStream_t s2;
    cudaEvent_t evFork, evJoin;
    cudaStreamCreateWithFlags(&s2, cudaStreamNonBlocking);
    cudaEventCreateWithFlags(&evFork, cudaEventDisableTiming);
    cudaEventCreateWithFlags(&evJoin, cudaEventDisableTiming);

    // fork s2 off the (capturing) default stream
    cudaEventRecord(evFork, 0);
    cudaStreamWaitEvent(s2, evFork, 0);

    // chain B: edge pipeline on s2
    probe_init_kernel<<<(N + 255) / 256, 256, 0, s2>>>((const unsigned int*)edges, E, N);
    hist_kernel<<<(E + 255) / 256, 256, 0, s2>>>(edges, E);
    scanA_kernel<<<nb, 256, 0, s2>>>(N);
    scanB_kernel<<<1, 256, 0, s2>>>(nb, N);
    scanC_kernel<<<nb, 256, 0, s2>>>(N);
    fill_kernel<<<(E + 255) / 256, 256, 0, s2>>>(edges, E);
    cudaEventRecord(evJoin, s2);

    // chain A: gemm on the default stream (concurrent with chain B)
    gemm_kernel<<<(N + BM - 1) / BM, 256, GEMM_SMEM_BYTES>>>(x, W, att_src, att_dst, N);

    // join, then aggregate (needs both chains)
    cudaStreamWaitEvent(0, evJoin, 0);
    aggregate_kernel<<<(N + 7) / 8, 256>>>(bias, (float*)d_out, N);
}

// round 11
// speedup vs baseline: 1.1921x; 1.0373x over previous
#include <cuda_runtime.h>
#include <cuda_pipeline.h>
#include <mma.h>
#include <math.h>

using namespace nvcuda;

#define NMAX   50000
#define EMAX   800000
#define TOTMAX (NMAX + EMAX)
#define F      128
#define NPAD   (NMAX + 128)   // slack so tail-block wmma stores can't overflow

// ---------------- device scratch (no allocations allowed) ----------------
__device__ float g_xp[NPAD * F];        // x @ W
__device__ float g_asrc[NMAX];          // xp . att_src
__device__ float g_adst[NMAX];          // xp . att_dst
__device__ int   g_deg[NMAX];           // per-dst degree (incl self loop)
__device__ int   g_offs[NMAX + 1];      // CSR offsets
__device__ int   g_rank[EMAX];          // per-edge rank within its dst segment
__device__ int   g_csr[TOTMAX];         // CSR: source node per slot
__device__ int   g_bsum[256];           // scan: per-block sums
__device__ int   g_is64;                // edge_index dtype flag

// ---------------- fused probe (1 warp of block 0) + degree init ----------------
__global__ void probe_init_kernel(const unsigned int* __restrict__ w, int E, int N) {
    int i = blockIdx.x * blockDim.x + threadIdx.x;
    if (i < N) g_deg[i] = 1;                       // self loop
    if (blockIdx.x == 0 && threadIdx.x < 32) {
        int samples = E < 1024 ? E : 1024;
        int bad = 0;
        for (int k = threadIdx.x; k < samples; k += 32)
            bad |= (w[2 * k + 1] != 0u) ? 1 : 0;
        unsigned int b = __ballot_sync(0xffffffffu, bad);
        if (threadIdx.x == 0) g_is64 = (b == 0u) ? 1 : 0;
    }
}

__device__ __forceinline__ int edge_at(const void* ebuf, long long idx, int is64) {
    if (is64) return (int)((const long long*)ebuf)[idx];
    return ((const int*)ebuf)[idx];
}

// ---------------- histogram of dst + per-edge rank ----------------
__global__ void hist_kernel(const void* __restrict__ edges, int E) {
    int e = blockIdx.x * blockDim.x + threadIdx.x;
    if (e >= E) return;
    int is64 = g_is64;
    int d = edge_at(edges, (long long)E + e, is64);
    g_rank[e] = atomicAdd(&g_deg[d], 1);   // old value >= 1 (slot 0 = self loop)
}

// ---------------- parallel scan: A) block sums ----------------
__global__ void scanA_kernel(int N) {
    __shared__ int sh[256];
    int t = threadIdx.x;
    int i = blockIdx.x * 256 + t;
    sh[t] = (i < N) ? g_deg[i] : 0;
    __syncthreads();
    for (int o = 128; o; o >>= 1) {
        if (t < o) sh[t] += sh[t + o];
        __syncthreads();
    }
    if (t == 0) g_bsum[blockIdx.x] = sh[0];
}

// ---------------- GEMM (wmma tf32, cp.async, W converted once in smem) --------
#define BM 128
#define BK 32
#define LDA 40    // 32 + 8 pad
#define LDB 136   // 128 + 8 pad
#define GEMM_SMEM_FLOATS (128 * LDB + 2 * BM * LDA)
#define GEMM_SMEM_BYTES  (GEMM_SMEM_FLOATS * 4)

__global__ __launch_bounds__(256, 2)
void gemm_kernel(const float* __restrict__ x, const float* __restrict__ W,
                 const float* __restrict__ att_src, const float* __restrict__ att_dst,
                 int N) {
    extern __shared__ float smem[];
    float* Ws = smem;                    // [128][LDB], tf32 after one-shot convert
    float* As = smem + 128 * LDB;        // [2][BM][LDA], raw fp32

    int tid  = threadIdx.x;
    int warp = tid >> 5;
    int lane = tid & 31;
    int warp_m = warp >> 1;
    int warp_n = warp & 1;
    int row0 = blockIdx.x * BM;

    auto stageA = [&](int kb, int buf) {
        float* base = As + buf * BM * LDA;
#pragma unroll
        for (int it = 0; it < 4; it++) {
            int item = tid + it * 256;       // 1024 items = 128 rows x 8 float4
            int m = item >> 3, kq = item & 7;
            int gr = row0 + m;
            float* dst = base + m * LDA + kq * 4;
            if (gr < N) {
                __pipeline_memcpy_async(dst, x + (long long)gr * F + kb * 32 + kq * 4, 16);
            } else {
                dst[0] = 0.f; dst[1] = 0.f; dst[2] = 0.f; dst[3] = 0.f;
            }
        }
        __pipeline_commit();
    };

    stageA(0, 0);
#pragma unroll
    for (int it = 0; it < 16; it++) {
        int item = tid + it * 256;
        int k = item >> 5, nq = item & 31;
        __pipeline_memcpy_async(Ws + k * LDB + nq * 4, W + (long long)k * F + nq * 4, 16);
    }
    __pipeline_commit();

    wmma::fragment<wmma::accumulator, 16, 16, 8, float> acc[2][4];
#pragma unroll
    for (int mt = 0; mt < 2; mt++)
#pragma unroll
        for (int nt = 0; nt < 4; nt++)
            wmma::fill_fragment(acc[mt][nt], 0.0f);

    __pipeline_wait_prior(0);
    __syncthreads();

    // one-shot in-place tf32 conversion of W (valid 128x128 region)
#pragma unroll
    for (int it = 0; it < 16; it++) {
        int item = tid + it * 256;
        int k = item >> 5, nq = item & 31;
        float* p = Ws + k * LDB + nq * 4;
        float4 v = *(float4*)p;
        v.x = wmma::__float_to_tf32(v.x);
        v.y = wmma::__float_to_tf32(v.y);
        v.z = wmma::__float_to_tf32(v.z);
        v.w = wmma::__float_to_tf32(v.w);
        *(float4*)p = v;
    }
    __syncthreads();

    for (int kb = 0; kb < 4; kb++) {
        if (kb < 3) stageA(kb + 1, (kb + 1) & 1);
        const float* Abuf = As + (kb & 1) * BM * LDA;

#pragma unroll
        for (int kk = 0; kk < 4; kk++) {
            wmma::fragment<wmma::matrix_a, 16, 16, 8, wmma::precision::tf32, wmma::row_major> af[2];
            wmma::fragment<wmma::matrix_b, 16, 16, 8, wmma::precision::tf32, wmma::row_major> bf[4];
#pragma unroll
            for (int mt = 0; mt < 2; mt++) {
                wmma::load_matrix_sync(af[mt], Abuf + (warp_m * 32 + mt * 16) * LDA + kk * 8, LDA);
#pragma unroll
                for (int i = 0; i < af[mt].num_elements; i++)
                    af[mt].x[i] = wmma::__float_to_tf32(af[mt].x[i]);
            }
#pragma unroll
            for (int nt = 0; nt < 4; nt++)
                wmma::load_matrix_sync(bf[nt], Ws + (kb * 32 + kk * 8) * LDB + warp_n * 64 + nt * 16, LDB);
#pragma unroll
            for (int mt = 0; mt < 2; mt++)
#pragma unroll
                for (int nt = 0; nt < 4; nt++)
                    wmma::mma_sync(acc[mt][nt], af[mt], bf[nt], acc[mt][nt]);
        }

        if (kb < 3) { __pipeline_wait_prior(0); __syncthreads(); }
    }

#pragma unroll
    for (int mt = 0; mt < 2; mt++)
#pragma unroll
        for (int nt = 0; nt < 4; nt++)
            wmma::store_matrix_sync(
                &g_xp[(long long)(row0 + warp_m * 32 + mt * 16) * F + warp_n * 64 + nt * 16],
                acc[mt][nt], F, wmma::mem_row_major);

    __syncthreads();

    // fused attention dots: warp w handles rows row0 + w*16 .. +15
    {
        float4 a = ((const float4*)att_src)[lane];
        float4 b = ((const float4*)att_dst)[lane];
        const float4* xp4 = (const float4*)g_xp;
#pragma unroll
        for (int r = 0; r < 16; r++) {
            int gr = row0 + warp * 16 + r;
            if (gr >= N) break;
            float4 v = xp4[(long long)gr * 32 + lane];
            float ps = v.x * a.x + v.y * a.y + v.z * a.z + v.w * a.w;
            float pd = v.x * b.x + v.y * b.y + v.z * b.z + v.w * b.w;
#pragma unroll
            for (int o = 16; o; o >>= 1) {
                ps += __shfl_down_sync(0xffffffffu, ps, o);
                pd += __shfl_down_sync(0xffffffffu, pd, o);
            }
            if (lane == 0) { g_asrc[gr] = ps; g_adst[gr] = pd; }
        }
    }
}

// ---------------- scan C': redundant scan of block sums + apply ----------------
__global__ void scanC_kernel(int nb, int N) {
    __shared__ int sb[256];
    __shared__ int sh[256];
    int t = threadIdx.x;

    // every block scans the (<=256) block sums itself
    sb[t] = (t < nb) ? g_bsum[t] : 0;
    __syncthreads();
    for (int o = 1; o < 256; o <<= 1) {
        int u = (t >= o) ? sb[t - o] : 0;
        __syncthreads();
        sb[t] += u;
        __syncthreads();
    }
    int myboff = (blockIdx.x == 0) ? 0 : sb[blockIdx.x - 1];
    if (blockIdx.x == 0 && t == 255) g_offs[N] = sb[255];

    int i = blockIdx.x * 256 + t;
    int v = (i < N) ? g_deg[i] : 0;
    sh[t] = v;
    __syncthreads();
    for (int o = 1; o < 256; o <<= 1) {
        int u = (t >= o) ? sh[t - o] : 0;
        __syncthreads();
        sh[t] += u;
        __syncthreads();
    }
    if (i < N) {
        int off = myboff + sh[t] - v;
        g_offs[i] = off;
        g_csr[off] = i;                      // self loop at slot 0 of segment
    }
}

// ---------------- CSR fill (atomic-free via precomputed rank) ----------------
__global__ void fill_kernel(const void* __restrict__ edges, int E) {
    int e = blockIdx.x * blockDim.x + threadIdx.x;
    if (e >= E) return;
    int is64 = g_is64;
    int s = edge_at(edges, e, is64);
    int d = edge_at(edges, (long long)E + e, is64);
    g_csr[__ldg(&g_offs[d]) + g_rank[e]] = s;
}

// ---------------- aggregate: warp per dst, chunked cooperative prefetch -------
__global__ void aggregate_kernel(const float* __restrict__ bias,
                                 float* __restrict__ out, int N) {
    int warp = (blockIdx.x * blockDim.x + threadIdx.x) >> 5;
    int lane = threadIdx.x & 31;
    if (warp >= N) return;

    int beg = g_offs[warp];
    int end = g_offs[warp + 1];
    float adi = g_adst[warp];

    float s = 0.f;
    float4 acc = make_float4(0.f, 0.f, 0.f, 0.f);
    const float4* xp4 = (const float4*)g_xp;

    for (int c = beg; c < end; c += 32) {
        int idx = c + lane;
        bool valid = idx < end;
        int j = __ldg(&g_csr[valid ? idx : beg]);
        float e = __ldg(&g_asrc[j]) + adi;
        e = fmaxf(e, 0.2f * e);              // leaky_relu(0.2)
        float p = valid ? __expf(e) : 0.f;

        int cnt = end - c; if (cnt > 32) cnt = 32;
#pragma unroll 8
        for (int t = 0; t < cnt; t++) {
            int jj   = __shfl_sync(0xffffffffu, j, t);
            float pp = __shfl_sync(0xffffffffu, p, t);
            float4 xv = xp4[(long long)jj * 32 + lane];
            s += pp;
            acc.x = fmaf(pp, xv.x, acc.x);
            acc.y = fmaf(pp, xv.y, acc.y);
            acc.z = fmaf(pp, xv.z, acc.z);
            acc.w = fmaf(pp, xv.w, acc.w);
        }
    }

    float inv = 1.0f / s;
    float4 b = ((const float4*)bias)[lane];
    float4 o;
    o.x = fmaf(acc.x, inv, b.x);
    o.y = fmaf(acc.y, inv, b.y);
    o.z = fmaf(acc.z, inv, b.z);
    o.w = fmaf(acc.w, inv, b.w);
    ((float4*)out)[(long long)warp * 32 + lane] = o;
}

// ---------------- launch: fork-join over a second stream ----------------
extern "C" void kernel_launch(void* const* d_in, const int* in_sizes, int n_in,
                              void* d_out, int out_size) {
    const float* x       = (const float*)d_in[0];
    const float* W       = (const float*)d_in[1];
    const float* att_src = (const float*)d_in[2];
    const float* att_dst = (const float*)d_in[3];
    const float* bias    = (const float*)d_in[4];
    const void*  edges   = d_in[5];

    int N = in_sizes[0] / F;
    int E = in_sizes[5] / 2;
    if (N > NMAX) N = NMAX;
    if (E > EMAX) E = EMAX;

    int nb = (N + 255) / 256;   // scan blocks (<= 256)

    cudaFuncSetAttribute(gemm_kernel, cudaFuncAttributeMaxDynamicSharedMemorySize,
                         GEMM_SMEM_BYTES);

    cudaStream_t s2;
    cudaEvent_t evFork, evJoin;
    cudaStreamCreateWithFlags(&s2, cudaStreamNonBlocking);
    cudaEventCreateWithFlags(&evFork, cudaEventDisableTiming);
    cudaEventCreateWithFlags(&evJoin, cudaEventDisableTiming);

    cudaEventRecord(evFork, 0);
    cudaStreamWaitEvent(s2, evFork, 0);

    // enqueue order: probe(0), hist(1), scanA(2), gemm(3) -> ncu idx-3 = gemm
    probe_init_kernel<<<(N + 255) / 256, 256, 0, s2>>>((const unsigned int*)edges, E, N);
    hist_kernel<<<(E + 255) / 256, 256, 0, s2>>>(edges, E);
    scanA_kernel<<<nb, 256, 0, s2>>>(N);
    gemm_kernel<<<(N + BM - 1) / BM, 256, GEMM_SMEM_BYTES>>>(x, W, att_src, att_dst, N);
    scanC_kernel<<<nb, 256, 0, s2>>>(nb, N);
    fill_kernel<<<(E + 255) / 256, 256, 0, s2>>>(edges, E);
    cudaEventRecord(evJoin, s2);

    cudaStreamWaitEvent(0, evJoin, 0);
    aggregate_kernel<<<(N + 7) / 8, 256>>>(bias, (float*)d_out, N);
}